// round 6
// baseline (speedup 1.0000x reference)
#include <cuda_runtime.h>
#include <cuda_bf16.h>
#include <cstdint>

// Problem constants
#define BB 512
#define DD 128
#define CC 100000
#define TC 32                      // proxies per c-tile (100000 = 3125*32 exact)
#define NT (CC / TC)               // 3125 tiles
#define ATT_EPS 1e-5f

// Scratch (device globals; no allocations allowed)
__device__ float g_Xn[BB * DD];
__device__ float g_Pb[BB * DD];
__device__ float g_diag[BB];
__device__ float g_att[BB * BB];
__device__ float g_rowsum[BB];     // rowsum[k] = sum_j att[k, j]
__device__ float g_Dt[BB];
__device__ float g_Z[BB];
__device__ __nv_bfloat16 g_Xs16[BB * DD];

// ---------------------------------------------------------------------------
// helpers
// ---------------------------------------------------------------------------
__device__ __forceinline__ uint32_t s2u(const void* p) {
    uint32_t a;
    asm("{ .reg .u64 t; cvta.to.shared.u64 t, %1; cvt.u32.u64 %0, t; }"
        : "=r"(a) : "l"(p));
    return a;
}

__device__ __forceinline__ float bred128(float v, float* s4) {
#pragma unroll
    for (int o = 16; o; o >>= 1) v += __shfl_xor_sync(0xffffffffu, v, o);
    __syncthreads();
    if ((threadIdx.x & 31) == 0) s4[threadIdx.x >> 5] = v;
    __syncthreads();
    return s4[0] + s4[1] + s4[2] + s4[3];
}

__device__ __forceinline__ void mma_bf16(float* acc, uint32_t a0, uint32_t a1,
                                         uint32_t a2, uint32_t a3,
                                         uint32_t b0, uint32_t b1) {
    asm volatile(
        "mma.sync.aligned.m16n8k16.row.col.f32.bf16.bf16.f32 "
        "{%0,%1,%2,%3}, {%4,%5,%6,%7}, {%8,%9}, {%0,%1,%2,%3};\n"
        : "+f"(acc[0]), "+f"(acc[1]), "+f"(acc[2]), "+f"(acc[3])
        : "r"(a0), "r"(a1), "r"(a2), "r"(a3), "r"(b0), "r"(b1));
}

__device__ __forceinline__ void ldsm4(uint32_t addr, uint32_t* r) {
    asm volatile("ldmatrix.sync.aligned.m8n8.x4.shared.b16 {%0,%1,%2,%3}, [%4];"
                 : "=r"(r[0]), "=r"(r[1]), "=r"(r[2]), "=r"(r[3]) : "r"(addr));
}

__device__ __forceinline__ float ex2f(float x) {
    float r;
    asm("ex2.approx.ftz.f32 %0, %1;" : "=f"(r) : "f"(x));
    return r;
}

__device__ __forceinline__ uint32_t f2b2(float a, float b) {
    __nv_bfloat162 h = __floats2bfloat162_rn(a, b);
    return *(uint32_t*)&h;
}

// Robust class-id fetch (JAX x64-disabled materializes int32 for declared int64)
__device__ __forceinline__ int fetch_T(const int* T32, int b, int is64) {
    int t = is64 ? T32[2 * b] : T32[b];
    return min(max(t, 0), CC - 1);
}
__device__ __forceinline__ int detect_i64_block(const int* T32) {
    int ok = 1;
    for (int i = threadIdx.x; i < BB; i += blockDim.x)
        if (T32[2 * i + 1] != 0) ok = 0;
    return __syncthreads_and(ok);
}

// ---------------------------------------------------------------------------
// K1: Xn = l2norm(X); Pb = l2norm(proxies[T]); diag = <Pb,Xn>; zero Z/rowsum
// ---------------------------------------------------------------------------
__global__ void k_prep(const float* __restrict__ X,
                       const int* __restrict__ T32,
                       const float* __restrict__ proxies) {
    __shared__ float s4[4];
    int b = blockIdx.x, d = threadIdx.x;
    int is64 = detect_i64_block(T32);

    float x = X[b * DD + d];
    float s = bred128(x * x, s4);
    float xn = x / fmaxf(sqrtf(s), 1e-12f);
    g_Xn[b * DD + d] = xn;

    int t = fetch_T(T32, b, is64);
    float p = proxies[(size_t)t * DD + d];
    float s2 = bred128(p * p, s4);
    float pb = p / fmaxf(sqrtf(s2), 1e-12f);
    g_Pb[b * DD + d] = pb;

    float dg = bred128(pb * xn, s4);
    if (d == 0) g_diag[b] = dg;
    if (b < 4) { g_rowsum[b * DD + d] = 0.f; }
    if (d == 0) g_Z[b] = 0.f;
}

// ---------------------------------------------------------------------------
// K2: att[b,j] = relu(0.5*(Pb[b].Xn[j] + diag[j])) + relu(Xn[b].Xn[j])
//     + atomic accumulation of ROW sums (sum over j at fixed b)
// ---------------------------------------------------------------------------
#define SMEM_ATT ((3 * 32 * 129 + 32 + 32) * 4)
__global__ void k_att() {
    extern __shared__ float smf[];
    float* PbS = smf;
    float* XnA = smf + 32 * 129;
    float* XnB = smf + 2 * 32 * 129;
    float* dgS = smf + 3 * 32 * 129;
    float* rsum = smf + 3 * 32 * 129 + 32;

    int tid = threadIdx.x;
    int b0 = blockIdx.y * 32, j0 = blockIdx.x * 32;
    for (int i = tid; i < 32 * DD; i += 256) {
        int r = i >> 7, d = i & 127;
        PbS[r * 129 + d] = g_Pb[(b0 + r) * DD + d];
        XnA[r * 129 + d] = g_Xn[(b0 + r) * DD + d];
        XnB[r * 129 + d] = g_Xn[(j0 + r) * DD + d];
    }
    if (tid < 32) { dgS[tid] = g_diag[j0 + tid]; rsum[tid] = 0.f; }
    __syncthreads();

    int tx = (tid & 15) * 2, ty = (tid >> 4) * 2;
    float apb00 = 0, apb01 = 0, apb10 = 0, apb11 = 0;
    float axx00 = 0, axx01 = 0, axx10 = 0, axx11 = 0;
#pragma unroll 4
    for (int d = 0; d < DD; d++) {
        float p0 = PbS[ty * 129 + d], p1 = PbS[(ty + 1) * 129 + d];
        float a0 = XnA[ty * 129 + d], a1 = XnA[(ty + 1) * 129 + d];
        float b0v = XnB[tx * 129 + d], b1v = XnB[(tx + 1) * 129 + d];
        apb00 += p0 * b0v; apb01 += p0 * b1v;
        apb10 += p1 * b0v; apb11 += p1 * b1v;
        axx00 += a0 * b0v; axx01 += a0 * b1v;
        axx10 += a1 * b0v; axx11 += a1 * b1v;
    }
    float dg0 = dgS[tx], dg1 = dgS[tx + 1];
    float a00 = fmaxf(0.5f * (apb00 + dg0), 0.f) + fmaxf(axx00, 0.f);
    float a01 = fmaxf(0.5f * (apb01 + dg1), 0.f) + fmaxf(axx01, 0.f);
    float a10 = fmaxf(0.5f * (apb10 + dg0), 0.f) + fmaxf(axx10, 0.f);
    float a11 = fmaxf(0.5f * (apb11 + dg1), 0.f) + fmaxf(axx11, 0.f);
    g_att[(b0 + ty) * BB + j0 + tx]         = a00;
    g_att[(b0 + ty) * BB + j0 + tx + 1]     = a01;
    g_att[(b0 + ty + 1) * BB + j0 + tx]     = a10;
    g_att[(b0 + ty + 1) * BB + j0 + tx + 1] = a11;

    // ROW sums: sum over columns j at fixed row b
    atomicAdd(&rsum[ty], a00 + a01);
    atomicAdd(&rsum[ty + 1], a10 + a11);
    __syncthreads();
    if (tid < 32) atomicAdd(&g_rowsum[b0 + tid], rsum[tid]);
}

// ---------------------------------------------------------------------------
// K3: for 4 rows b per block: W[b,:] = sum_k att[b,k]/(rowsum[k]+eps) * Xn[k,:]
//     X2 = Xn + W; Xs = 3*l2norm(X2) -> bf16 ; Dt = relu(18 - 6*<Xs,Pb>)
// 128 blocks x 256 threads
// ---------------------------------------------------------------------------
__global__ void __launch_bounds__(256) k_xw() {
    __shared__ float ws[4][BB];
    __shared__ float4 part[8][4][32];
    __shared__ float wsA[8], wsB[8];
    int tid = threadIdx.x;
    int b0 = blockIdx.x * 4;
    int kp = tid >> 5, d4 = tid & 31;

    for (int i = tid; i < BB; i += 256) {
        float inv = 1.f / (g_rowsum[i] + ATT_EPS);
        ws[0][i] = g_att[(b0 + 0) * BB + i] * inv;
        ws[1][i] = g_att[(b0 + 1) * BB + i] * inv;
        ws[2][i] = g_att[(b0 + 2) * BB + i] * inv;
        ws[3][i] = g_att[(b0 + 3) * BB + i] * inv;
    }
    __syncthreads();

    const float4* Xn4 = (const float4*)g_Xn;
    float4 acc[4];
#pragma unroll
    for (int r = 0; r < 4; r++) acc[r] = make_float4(0.f, 0.f, 0.f, 0.f);
    int k0 = kp * 64;
#pragma unroll 4
    for (int kk = 0; kk < 64; kk++) {
        int k = k0 + kk;
        float4 x = Xn4[k * 32 + d4];
#pragma unroll
        for (int r = 0; r < 4; r++) {
            float wv = ws[r][k];
            acc[r].x += wv * x.x; acc[r].y += wv * x.y;
            acc[r].z += wv * x.z; acc[r].w += wv * x.w;
        }
    }
#pragma unroll
    for (int r = 0; r < 4; r++) part[kp][r][d4] = acc[r];
    __syncthreads();

    int row = tid >> 6, j = tid & 63;
    float s1 = 0.f, s2 = 0.f;
#pragma unroll
    for (int p = 0; p < 8; p++) {
        const float* pf = (const float*)part[p][row];
        s1 += pf[j];
        s2 += pf[j + 64];
    }
    float x2a = g_Xn[(b0 + row) * DD + j] + s1;
    float x2b = g_Xn[(b0 + row) * DD + j + 64] + s2;

    float ssq = x2a * x2a + x2b * x2b;
#pragma unroll
    for (int o = 16; o; o >>= 1) ssq += __shfl_xor_sync(0xffffffffu, ssq, o);
    if ((tid & 31) == 0) wsA[tid >> 5] = ssq;
    __syncthreads();
    float stot = wsA[row * 2] + wsA[row * 2 + 1];
    float sc = 3.f / fmaxf(sqrtf(stot), 1e-12f);
    float xsa = x2a * sc, xsb = x2b * sc;
    g_Xs16[(b0 + row) * DD + j] = __float2bfloat16(xsa);
    g_Xs16[(b0 + row) * DD + j + 64] = __float2bfloat16(xsb);

    float dp = xsa * g_Pb[(b0 + row) * DD + j] + xsb * g_Pb[(b0 + row) * DD + j + 64];
#pragma unroll
    for (int o = 16; o; o >>= 1) dp += __shfl_xor_sync(0xffffffffu, dp, o);
    if ((tid & 31) == 0) wsB[tid >> 5] = dp;
    __syncthreads();
    if (j == 0) {
        float dt = wsB[row * 2] + wsB[row * 2 + 1];
        g_Dt[b0 + row] = fmaxf(18.f - 6.f * dt, 0.f);
    }
}

// ---------------------------------------------------------------------------
// K4 (big): Z[b] += sum_c exp(-relu(18 - 2*<Xs[b], 3*l2norm(proxy_c)>))
// 2 CTAs per SM, each 256 threads (8 warps), each owning HALF the M-rows
// (half = blockIdx.x & 1). Both halves stream the same 32-proxy tiles
// (co-scheduled pair -> L2 hit for the second reader). Per CTA:
//   As 256x68 u32 (bf16 pairs) | Ps 32x68 | 2 x f32 staging 32x128
//   = 111104 B <= 113.6 KB  => 2 CTAs resident, cross-CTA phase overlap.
// Warp w owns rows half*256 + w*32 .. +32 (2 m-frags), all 32 tile-columns.
// cp.async refill mapping == conv read mapping (per-thread ownership) so the
// refill is issued inside the conv phase with no extra barrier.
// ---------------------------------------------------------------------------
#define STGF (TC * DD)                 // 4096 floats per staging buffer
#define SMEM_BIG (((BB / 2 + TC) * 68) * 4 + 2 * STGF * 4)

__global__ void __launch_bounds__(256, 2) k_big(const float* __restrict__ proxies) {
    extern __shared__ uint32_t smu[];
    uint32_t* As = smu;                            // 256 x 68
    uint32_t* Ps = smu + (BB / 2) * 68;            // 32 x 68
    float* Stg = (float*)(smu + (BB / 2 + TC) * 68);  // 2 x 32x128 f32

    const int tid = threadIdx.x;
    const int w = tid >> 5, lane = tid & 31, gid = lane >> 2, tig = lane & 3;
    const int grp = lane >> 3, lr = lane & 7;
    const uint32_t s_as = s2u(As), s_ps = s2u(Ps), s_st = s2u(Stg);

    const int half = blockIdx.x & 1;
    const int stride = gridDim.x >> 1;
    int t = blockIdx.x >> 1;

    // per-thread tile chunk: row cRow (0..31), 4 float4s at cSub*4..+4
    const int cRow = tid >> 3, cSub = tid & 7;
    const size_t gRowOff = (size_t)cRow * DD + cSub * 16;
    const uint32_t stOff = (uint32_t)(cRow * 32 + cSub * 4) * 16;

    // prologue: fill both staging buffers (exact tiling: no bounds checks)
#pragma unroll
    for (int j = 0; j < 4; j++) {
        const float4* g = (const float4*)(proxies + (size_t)t * TC * DD + gRowOff) + j;
        asm volatile("cp.async.cg.shared.global [%0], [%1], 16;"
                     :: "r"(s_st + stOff + j * 16), "l"(g));
    }
    asm volatile("cp.async.commit_group;");
    {
        int t1 = t + stride;
        if (t1 < NT) {
#pragma unroll
            for (int j = 0; j < 4; j++) {
                const float4* g = (const float4*)(proxies + (size_t)t1 * TC * DD + gRowOff) + j;
                asm volatile("cp.async.cg.shared.global [%0], [%1], 16;"
                             :: "r"(s_st + STGF * 4 + stOff + j * 16), "l"(g));
            }
        }
        asm volatile("cp.async.commit_group;");
    }

    // stage this half's Xs (bf16) into padded As
    const uint32_t* Xg = (const uint32_t*)g_Xs16 + half * (BB / 2) * (DD / 2);
    for (int i = tid; i < (BB / 2) * (DD / 2); i += 256)
        As[(i >> 6) * 68 + (i & 63)] = Xg[i];

    float rs[2][2];
    rs[0][0] = rs[0][1] = rs[1][0] = rs[1][1] = 0.f;

    // ldmatrix address pieces
    const uint32_t aRowBase = (uint32_t)(w * 32 + (grp & 1) * 8 + lr);
    const uint32_t aKadd = (uint32_t)((grp >> 1) * 4);
    const uint32_t bRowBase = (uint32_t)((grp >> 1) * 8 + lr);
    const uint32_t bKadd = (uint32_t)((grp & 1) * 4);

    // folded constants: exp(-relu(18-2acc)) = 2^min(2*log2e*acc - 18*log2e, 0)
    const float C2L = 2.8853900817779268f;     // 2*log2(e)
    const float SXL = 25.96851073600134f;      // 18*log2(e)

    int cur = 0;
    while (t < NT) {
        asm volatile("cp.async.wait_group 1;");
        __syncthreads();   // staging[cur] (tile t) visible; prev mma done

        // conv: read own chunk -> refill own chunk -> normalize -> Ps
        {
            const float4* Sg = (const float4*)(Stg + cur * STGF);
            float4 q0 = Sg[cRow * 32 + cSub * 4 + 0];
            float4 q1 = Sg[cRow * 32 + cSub * 4 + 1];
            float4 q2 = Sg[cRow * 32 + cSub * 4 + 2];
            float4 q3 = Sg[cRow * 32 + cSub * 4 + 3];

            // refill this exact chunk with tile t+2*stride (per-thread safe)
            int t2 = t + 2 * stride;
            if (t2 < NT) {
#pragma unroll
                for (int j = 0; j < 4; j++) {
                    const float4* g = (const float4*)(proxies + (size_t)t2 * TC * DD + gRowOff) + j;
                    asm volatile("cp.async.cg.shared.global [%0], [%1], 16;"
                                 :: "r"(s_st + cur * STGF * 4 + stOff + j * 16), "l"(g));
                }
            }
            asm volatile("cp.async.commit_group;");

            float s = q0.x * q0.x + q0.y * q0.y + q0.z * q0.z + q0.w * q0.w
                    + q1.x * q1.x + q1.y * q1.y + q1.z * q1.z + q1.w * q1.w
                    + q2.x * q2.x + q2.y * q2.y + q2.z * q2.z + q2.w * q2.w
                    + q3.x * q3.x + q3.y * q3.y + q3.z * q3.z + q3.w * q3.w;
            s += __shfl_xor_sync(0xffffffffu, s, 4);
            s += __shfl_xor_sync(0xffffffffu, s, 2);
            s += __shfl_xor_sync(0xffffffffu, s, 1);
            float sc = (s > 0.f) ? 3.f * rsqrtf(s) : 0.f;
            uint4 o0, o1;
            o0.x = f2b2(q0.x * sc, q0.y * sc); o0.y = f2b2(q0.z * sc, q0.w * sc);
            o0.z = f2b2(q1.x * sc, q1.y * sc); o0.w = f2b2(q1.z * sc, q1.w * sc);
            o1.x = f2b2(q2.x * sc, q2.y * sc); o1.y = f2b2(q2.z * sc, q2.w * sc);
            o1.z = f2b2(q3.x * sc, q3.y * sc); o1.w = f2b2(q3.z * sc, q3.w * sc);
            uint4* dst = (uint4*)(Ps + cRow * 68 + cSub * 8);
            dst[0] = o0; dst[1] = o1;
        }
        __syncthreads();   // Ps ready

        float acc[2][4][4];
#pragma unroll
        for (int mf = 0; mf < 2; mf++)
#pragma unroll
            for (int n = 0; n < 4; n++) {
                acc[mf][n][0] = 0.f; acc[mf][n][1] = 0.f;
                acc[mf][n][2] = 0.f; acc[mf][n][3] = 0.f;
            }

#pragma unroll
        for (int ks = 0; ks < 8; ks++) {
            uint32_t kb = ks * 8;
            uint32_t a[2][4];
#pragma unroll
            for (int mf = 0; mf < 2; mf++)
                ldsm4(s_as + ((aRowBase + mf * 16) * 68 + kb + aKadd) * 4, a[mf]);
            uint32_t bq[4][2];
#pragma unroll
            for (int np = 0; np < 2; np++) {
                uint32_t r4[4];
                ldsm4(s_ps + ((bRowBase + np * 16) * 68 + kb + bKadd) * 4, r4);
                bq[2 * np][0] = r4[0]; bq[2 * np][1] = r4[1];
                bq[2 * np + 1][0] = r4[2]; bq[2 * np + 1][1] = r4[3];
            }
#pragma unroll
            for (int mf = 0; mf < 2; mf++)
#pragma unroll
                for (int n = 0; n < 4; n++)
                    mma_bf16(acc[mf][n], a[mf][0], a[mf][1], a[mf][2], a[mf][3],
                             bq[n][0], bq[n][1]);
        }

        // epilogue: rs += 2^min(C2L*acc - SXL, 0)
#pragma unroll
        for (int mf = 0; mf < 2; mf++) {
#pragma unroll
            for (int n = 0; n < 4; n++) {
                float e0 = fminf(fmaf(C2L, acc[mf][n][0], -SXL), 0.f);
                float e1 = fminf(fmaf(C2L, acc[mf][n][1], -SXL), 0.f);
                float e2 = fminf(fmaf(C2L, acc[mf][n][2], -SXL), 0.f);
                float e3 = fminf(fmaf(C2L, acc[mf][n][3], -SXL), 0.f);
                rs[mf][0] += ex2f(e0) + ex2f(e1);
                rs[mf][1] += ex2f(e2) + ex2f(e3);
            }
        }

        cur ^= 1;
        t += stride;
    }

    // flush: quad-reduce over tig, one atomicAdd per row
#pragma unroll
    for (int mf = 0; mf < 2; mf++) {
#pragma unroll
        for (int h = 0; h < 2; h++) {
            float v = rs[mf][h];
            v += __shfl_xor_sync(0xffffffffu, v, 1);
            v += __shfl_xor_sync(0xffffffffu, v, 2);
            if (tig == 0)
                atomicAdd(&g_Z[half * (BB / 2) + w * 32 + mf * 16 + h * 8 + gid], v);
        }
    }
}

// ---------------------------------------------------------------------------
// K5: out = mean_b( Dt[b] + log(Z[b]) )
// ---------------------------------------------------------------------------
__global__ void k_final(float* __restrict__ out) {
    __shared__ float sw[16];
    int tid = threadIdx.x;
    float v = g_Dt[tid] + logf(g_Z[tid]);
#pragma unroll
    for (int o = 16; o; o >>= 1) v += __shfl_xor_sync(0xffffffffu, v, o);
    if ((tid & 31) == 0) sw[tid >> 5] = v;
    __syncthreads();
    if (tid < 32) {
        float u = (tid < 16) ? sw[tid] : 0.f;
#pragma unroll
        for (int o = 8; o; o >>= 1) u += __shfl_xor_sync(0xffffffffu, u, o);
        if (tid == 0) out[0] = u / (float)BB;
    }
}

// ---------------------------------------------------------------------------
// launch
// ---------------------------------------------------------------------------
extern "C" void kernel_launch(void* const* d_in, const int* in_sizes, int n_in,
                              void* d_out, int out_size) {
    const float* X = (const float*)d_in[0];
    const int* T32 = (const int*)d_in[2];
    const float* proxies = (const float*)d_in[3];
    float* out = (float*)d_out;

    int sms = 0;
    cudaDeviceGetAttribute(&sms, cudaDevAttrMultiProcessorCount, 0);
    if (sms <= 0) sms = 148;
    cudaFuncSetAttribute(k_big, cudaFuncAttributeMaxDynamicSharedMemorySize, SMEM_BIG);
    cudaFuncSetAttribute(k_att, cudaFuncAttributeMaxDynamicSharedMemorySize, SMEM_ATT);

    k_prep<<<BB, DD>>>(X, T32, proxies);
    dim3 ga(16, 16);
    k_att<<<ga, 256, SMEM_ATT>>>();
    k_xw<<<128, 256>>>();
    k_big<<<sms * 2, 256, SMEM_BIG>>>(proxies);
    k_final<<<1, BB>>>(out);
}

// round 9
// speedup vs baseline: 1.0671x; 1.0671x over previous
#include <cuda_runtime.h>
#include <cuda_bf16.h>
#include <cstdint>

// Problem constants
#define BB 512
#define DD 128
#define CC 100000
#define TCB 64                     // proxies per tile in k_big
#define NTB ((CC + TCB - 1) / TCB) // 1563 tiles (last zero-padded)
#define ATT_EPS 1e-5f

// Scratch (device globals; no allocations allowed)
__device__ float g_Xn[BB * DD];
__device__ float g_Pb[BB * DD];
__device__ float g_diag[BB];
__device__ float g_att[BB * BB];
__device__ float g_rowsum[BB];
__device__ float g_Dt[BB];
__device__ float g_Z[BB];
__device__ __align__(16) __nv_bfloat16 g_Xs16[BB * DD];
__device__ __align__(16) __nv_bfloat16 g_pn16[CC * DD];   // 3 * l2norm(proxies), bf16

// ---------------------------------------------------------------------------
// helpers
// ---------------------------------------------------------------------------
__device__ __forceinline__ uint32_t s2u(const void* p) {
    uint32_t a;
    asm("{ .reg .u64 t; cvta.to.shared.u64 t, %1; cvt.u32.u64 %0, t; }"
        : "=r"(a) : "l"(p));
    return a;
}

__device__ __forceinline__ float bred128(float v, float* s4) {
#pragma unroll
    for (int o = 16; o; o >>= 1) v += __shfl_xor_sync(0xffffffffu, v, o);
    __syncthreads();
    if ((threadIdx.x & 31) == 0) s4[threadIdx.x >> 5] = v;
    __syncthreads();
    return s4[0] + s4[1] + s4[2] + s4[3];
}

__device__ __forceinline__ void mma_bf16(float* acc, uint32_t a0, uint32_t a1,
                                         uint32_t a2, uint32_t a3,
                                         uint32_t b0, uint32_t b1) {
    asm volatile(
        "mma.sync.aligned.m16n8k16.row.col.f32.bf16.bf16.f32 "
        "{%0,%1,%2,%3}, {%4,%5,%6,%7}, {%8,%9}, {%0,%1,%2,%3};\n"
        : "+f"(acc[0]), "+f"(acc[1]), "+f"(acc[2]), "+f"(acc[3])
        : "r"(a0), "r"(a1), "r"(a2), "r"(a3), "r"(b0), "r"(b1));
}

__device__ __forceinline__ void ldsm4(uint32_t addr, uint32_t* r) {
    asm volatile("ldmatrix.sync.aligned.m8n8.x4.shared.b16 {%0,%1,%2,%3}, [%4];"
                 : "=r"(r[0]), "=r"(r[1]), "=r"(r[2]), "=r"(r[3]) : "r"(addr));
}

__device__ __forceinline__ float ex2f(float x) {
    float r;
    asm("ex2.approx.ftz.f32 %0, %1;" : "=f"(r) : "f"(x));
    return r;
}

__device__ __forceinline__ uint32_t f2b2(float a, float b) {
    __nv_bfloat162 h = __floats2bfloat162_rn(a, b);
    return *(uint32_t*)&h;
}

// Robust class-id fetch (JAX x64-disabled materializes int32 for declared int64)
__device__ __forceinline__ int fetch_T(const int* T32, int b, int is64) {
    int t = is64 ? T32[2 * b] : T32[b];
    return min(max(t, 0), CC - 1);
}
__device__ __forceinline__ int detect_i64_block(const int* T32) {
    int ok = 1;
    for (int i = threadIdx.x; i < BB; i += blockDim.x)
        if (T32[2 * i + 1] != 0) ok = 0;
    return __syncthreads_and(ok);
}

// ---------------------------------------------------------------------------
// K0: g_pn16[c,:] = bf16( 3 * l2norm(proxies[c,:]) ). 3125 blocks x 256 thr,
// 8 threads per row (32 rows per block; 100000 = 3125*32 exact).
// ---------------------------------------------------------------------------
__global__ void __launch_bounds__(256) k_pnorm(const float* __restrict__ proxies) {
    int tid = threadIdx.x;
    int r = blockIdx.x * 32 + (tid >> 3);
    int sub = tid & 7;
    const float4* src = (const float4*)(proxies + (size_t)r * DD) + sub * 4;
    float4 q0 = src[0], q1 = src[1], q2 = src[2], q3 = src[3];
    float s = q0.x * q0.x + q0.y * q0.y + q0.z * q0.z + q0.w * q0.w
            + q1.x * q1.x + q1.y * q1.y + q1.z * q1.z + q1.w * q1.w
            + q2.x * q2.x + q2.y * q2.y + q2.z * q2.z + q2.w * q2.w
            + q3.x * q3.x + q3.y * q3.y + q3.z * q3.z + q3.w * q3.w;
    s += __shfl_xor_sync(0xffffffffu, s, 4);
    s += __shfl_xor_sync(0xffffffffu, s, 2);
    s += __shfl_xor_sync(0xffffffffu, s, 1);
    float sc = (s > 0.f) ? 3.f * rsqrtf(s) : 0.f;
    uint4 o0, o1;
    o0.x = f2b2(q0.x * sc, q0.y * sc); o0.y = f2b2(q0.z * sc, q0.w * sc);
    o0.z = f2b2(q1.x * sc, q1.y * sc); o0.w = f2b2(q1.z * sc, q1.w * sc);
    o1.x = f2b2(q2.x * sc, q2.y * sc); o1.y = f2b2(q2.z * sc, q2.w * sc);
    o1.z = f2b2(q3.x * sc, q3.y * sc); o1.w = f2b2(q3.z * sc, q3.w * sc);
    uint4* dst = (uint4*)(g_pn16 + (size_t)r * DD) + sub * 2;
    dst[0] = o0; dst[1] = o1;
}

// ---------------------------------------------------------------------------
// K1: Xn = l2norm(X); Pb = l2norm(proxies[T]); diag = <Pb,Xn>; zero Z/rowsum
// ---------------------------------------------------------------------------
__global__ void k_prep(const float* __restrict__ X,
                       const int* __restrict__ T32,
                       const float* __restrict__ proxies) {
    __shared__ float s4[4];
    int b = blockIdx.x, d = threadIdx.x;
    int is64 = detect_i64_block(T32);

    float x = X[b * DD + d];
    float s = bred128(x * x, s4);
    float xn = x / fmaxf(sqrtf(s), 1e-12f);
    g_Xn[b * DD + d] = xn;

    int t = fetch_T(T32, b, is64);
    float p = proxies[(size_t)t * DD + d];
    float s2 = bred128(p * p, s4);
    float pb = p / fmaxf(sqrtf(s2), 1e-12f);
    g_Pb[b * DD + d] = pb;

    float dg = bred128(pb * xn, s4);
    if (d == 0) g_diag[b] = dg;
    if (b < 4) { g_rowsum[b * DD + d] = 0.f; }
    if (d == 0) g_Z[b] = 0.f;
}

// ---------------------------------------------------------------------------
// K2: att[b,j] = relu(0.5*(Pb[b].Xn[j] + diag[j])) + relu(Xn[b].Xn[j])
//     + atomic accumulation of ROW sums
// ---------------------------------------------------------------------------
#define SMEM_ATT ((3 * 32 * 129 + 32 + 32) * 4)
__global__ void k_att() {
    extern __shared__ float smf[];
    float* PbS = smf;
    float* XnA = smf + 32 * 129;
    float* XnB = smf + 2 * 32 * 129;
    float* dgS = smf + 3 * 32 * 129;
    float* rsum = smf + 3 * 32 * 129 + 32;

    int tid = threadIdx.x;
    int b0 = blockIdx.y * 32, j0 = blockIdx.x * 32;
    for (int i = tid; i < 32 * DD; i += 256) {
        int r = i >> 7, d = i & 127;
        PbS[r * 129 + d] = g_Pb[(b0 + r) * DD + d];
        XnA[r * 129 + d] = g_Xn[(b0 + r) * DD + d];
        XnB[r * 129 + d] = g_Xn[(j0 + r) * DD + d];
    }
    if (tid < 32) { dgS[tid] = g_diag[j0 + tid]; rsum[tid] = 0.f; }
    __syncthreads();

    int tx = (tid & 15) * 2, ty = (tid >> 4) * 2;
    float apb00 = 0, apb01 = 0, apb10 = 0, apb11 = 0;
    float axx00 = 0, axx01 = 0, axx10 = 0, axx11 = 0;
#pragma unroll 4
    for (int d = 0; d < DD; d++) {
        float p0 = PbS[ty * 129 + d], p1 = PbS[(ty + 1) * 129 + d];
        float a0 = XnA[ty * 129 + d], a1 = XnA[(ty + 1) * 129 + d];
        float b0v = XnB[tx * 129 + d], b1v = XnB[(tx + 1) * 129 + d];
        apb00 += p0 * b0v; apb01 += p0 * b1v;
        apb10 += p1 * b0v; apb11 += p1 * b1v;
        axx00 += a0 * b0v; axx01 += a0 * b1v;
        axx10 += a1 * b0v; axx11 += a1 * b1v;
    }
    float dg0 = dgS[tx], dg1 = dgS[tx + 1];
    float a00 = fmaxf(0.5f * (apb00 + dg0), 0.f) + fmaxf(axx00, 0.f);
    float a01 = fmaxf(0.5f * (apb01 + dg1), 0.f) + fmaxf(axx01, 0.f);
    float a10 = fmaxf(0.5f * (apb10 + dg0), 0.f) + fmaxf(axx10, 0.f);
    float a11 = fmaxf(0.5f * (apb11 + dg1), 0.f) + fmaxf(axx11, 0.f);
    g_att[(b0 + ty) * BB + j0 + tx]         = a00;
    g_att[(b0 + ty) * BB + j0 + tx + 1]     = a01;
    g_att[(b0 + ty + 1) * BB + j0 + tx]     = a10;
    g_att[(b0 + ty + 1) * BB + j0 + tx + 1] = a11;

    atomicAdd(&rsum[ty], a00 + a01);
    atomicAdd(&rsum[ty + 1], a10 + a11);
    __syncthreads();
    if (tid < 32) atomicAdd(&g_rowsum[b0 + tid], rsum[tid]);
}

// ---------------------------------------------------------------------------
// K3: W[b,:] = sum_k att[b,k]/(rowsum[k]+eps) * Xn[k,:]; X2 = Xn + W;
//     Xs = 3*l2norm(X2) -> bf16 ; Dt = relu(18 - 6*<Xs,Pb>)
// ---------------------------------------------------------------------------
__global__ void __launch_bounds__(256) k_xw() {
    __shared__ float ws[4][BB];
    __shared__ float4 part[8][4][32];
    __shared__ float wsA[8], wsB[8];
    int tid = threadIdx.x;
    int b0 = blockIdx.x * 4;
    int kp = tid >> 5, d4 = tid & 31;

    for (int i = tid; i < BB; i += 256) {
        float inv = 1.f / (g_rowsum[i] + ATT_EPS);
        ws[0][i] = g_att[(b0 + 0) * BB + i] * inv;
        ws[1][i] = g_att[(b0 + 1) * BB + i] * inv;
        ws[2][i] = g_att[(b0 + 2) * BB + i] * inv;
        ws[3][i] = g_att[(b0 + 3) * BB + i] * inv;
    }
    __syncthreads();

    const float4* Xn4 = (const float4*)g_Xn;
    float4 acc[4];
#pragma unroll
    for (int r = 0; r < 4; r++) acc[r] = make_float4(0.f, 0.f, 0.f, 0.f);
    int k0 = kp * 64;
#pragma unroll 4
    for (int kk = 0; kk < 64; kk++) {
        int k = k0 + kk;
        float4 x = Xn4[k * 32 + d4];
#pragma unroll
        for (int r = 0; r < 4; r++) {
            float wv = ws[r][k];
            acc[r].x += wv * x.x; acc[r].y += wv * x.y;
            acc[r].z += wv * x.z; acc[r].w += wv * x.w;
        }
    }
#pragma unroll
    for (int r = 0; r < 4; r++) part[kp][r][d4] = acc[r];
    __syncthreads();

    int row = tid >> 6, j = tid & 63;
    float s1 = 0.f, s2 = 0.f;
#pragma unroll
    for (int p = 0; p < 8; p++) {
        const float* pf = (const float*)part[p][row];
        s1 += pf[j];
        s2 += pf[j + 64];
    }
    float x2a = g_Xn[(b0 + row) * DD + j] + s1;
    float x2b = g_Xn[(b0 + row) * DD + j + 64] + s2;

    float ssq = x2a * x2a + x2b * x2b;
#pragma unroll
    for (int o = 16; o; o >>= 1) ssq += __shfl_xor_sync(0xffffffffu, ssq, o);
    if ((tid & 31) == 0) wsA[tid >> 5] = ssq;
    __syncthreads();
    float stot = wsA[row * 2] + wsA[row * 2 + 1];
    float sc = 3.f / fmaxf(sqrtf(stot), 1e-12f);
    float xsa = x2a * sc, xsb = x2b * sc;
    g_Xs16[(b0 + row) * DD + j] = __float2bfloat16(xsa);
    g_Xs16[(b0 + row) * DD + j + 64] = __float2bfloat16(xsb);

    float dp = xsa * g_Pb[(b0 + row) * DD + j] + xsb * g_Pb[(b0 + row) * DD + j + 64];
#pragma unroll
    for (int o = 16; o; o >>= 1) dp += __shfl_xor_sync(0xffffffffu, dp, o);
    if ((tid & 31) == 0) wsB[tid >> 5] = dp;
    __syncthreads();
    if (j == 0) {
        float dt = wsB[row * 2] + wsB[row * 2 + 1];
        g_Dt[b0 + row] = fmaxf(18.f - 6.f * dt, 0.f);
    }
}

// ---------------------------------------------------------------------------
// K4 (big): Z[b] += sum_c exp(-relu(18 - 2*<Xs[b], pn[c]>))
// 512 threads (16 warps); warp w owns rows [w*32, w*32+32).
// B tiles stream as READY bf16 (g_pn16) via cp.async straight into the
// padded-68 ldmatrix layout: 512 threads x TWO 16B chunks = one 64x128 tile
// (64 rows x 256B data per row = 16 chunks/row; thread covers j and j+8).
// Ring-3 buffers; ONE wait_group + ONE __syncthreads per iteration:
//   iter i: wait_group 1 (tile T(i) landed) -> barrier (also orders iter
//   i-1's reads of buf[(i+2)%3]) -> refill buf[(i+2)%3] <- T(i+2) -> compute.
// smem: As 512x68 u32 = 139264 | B 3 x 64 x 272B = 52224  -> 191488 B
// ---------------------------------------------------------------------------
#define BROWB 272                       // bytes per padded B row (68 u32)
#define BBUFB (TCB * BROWB)             // 17408 bytes per B buffer
#define SMEM_BIG (BB * 68 * 4 + 3 * BBUFB)

__device__ __forceinline__ void cp_b(uint32_t s_b, int t, int buf, int tid) {
    if (t < NTB) {
        int r = tid >> 3, j = tid & 7;       // row 0..63, chunks j and j+8
        int gr = t * TCB + r;
        int ok = gr < CC;
        const char* src = (const char*)(g_pn16 + (size_t)(ok ? gr : 0) * DD);
        uint32_t dst = s_b + buf * BBUFB + r * BROWB;
        int sz = ok ? 16 : 0;                // sz=0 -> zero-fill (no dup rows)
        asm volatile("cp.async.cg.shared.global [%0], [%1], 16, %2;"
                     :: "r"(dst + j * 16), "l"(src + j * 16), "r"(sz));
        asm volatile("cp.async.cg.shared.global [%0], [%1], 16, %2;"
                     :: "r"(dst + (j + 8) * 16), "l"(src + (j + 8) * 16), "r"(sz));
    }
    asm volatile("cp.async.commit_group;");
}

__global__ void __launch_bounds__(512, 1) k_big() {
    extern __shared__ uint32_t smu[];
    uint32_t* As = smu;                      // 512 x 68
    const uint32_t s_as = s2u(As);
    const uint32_t s_b = s_as + BB * 68 * 4;

    const int tid = threadIdx.x;
    const int w = tid >> 5, lane = tid & 31, gid = lane >> 2, tig = lane & 3;
    const int grp = lane >> 3, lr = lane & 7;

    const int stride = gridDim.x;
    int t = blockIdx.x;

    // prologue: two B tiles in flight, stage A meanwhile
    cp_b(s_b, t, 0, tid);
    cp_b(s_b, t + stride, 1, tid);
    {
        const uint32_t* Xg = (const uint32_t*)g_Xs16;
        for (int i = tid; i < BB * (DD / 2); i += 512)
            As[(i >> 6) * 68 + (i & 63)] = Xg[i];
    }

    float rs[2][2];
    rs[0][0] = rs[0][1] = rs[1][0] = rs[1][1] = 0.f;

    // ldmatrix address pieces (identical to the verified R5 layout)
    const uint32_t aRowBase = (uint32_t)(w * 32 + (grp & 1) * 8 + lr);
    const uint32_t aKadd = (uint32_t)((grp >> 1) * 4);
    const uint32_t bRowBase = (uint32_t)((grp >> 1) * 8 + lr);
    const uint32_t bKadd = (uint32_t)((grp & 1) * 4);

    const float C2L = 2.8853900817779268f;   // 2*log2(e)
    const float SXL = 25.96851073600134f;    // 18*log2(e)

    int it = 0;
    for (; t < NTB; t += stride, it++) {
        asm volatile("cp.async.wait_group 1;");   // tile T(it) landed
        __syncthreads();                          // + iter it-1 reads done

        // refill the buffer iter it+2 will read (last read at iter it-1)
        cp_b(s_b, t + 2 * stride, (it + 2) % 3, tid);

        const uint32_t s_bb = s_b + (it % 3) * BBUFB;

        float acc[2][8][4];
#pragma unroll
        for (int mf = 0; mf < 2; mf++)
#pragma unroll
            for (int n = 0; n < 8; n++) {
                acc[mf][n][0] = 0.f; acc[mf][n][1] = 0.f;
                acc[mf][n][2] = 0.f; acc[mf][n][3] = 0.f;
            }

#pragma unroll
        for (int ks = 0; ks < 8; ks++) {
            uint32_t kb = ks * 8;
            uint32_t a[2][4];
#pragma unroll
            for (int mf = 0; mf < 2; mf++)
                ldsm4(s_as + ((aRowBase + mf * 16) * 68 + kb + aKadd) * 4, a[mf]);
            uint32_t bq[8][2];
#pragma unroll
            for (int np = 0; np < 4; np++) {
                uint32_t r4[4];
                ldsm4(s_bb + ((bRowBase + np * 16) * 68 + kb + bKadd) * 4, r4);
                bq[2 * np][0] = r4[0]; bq[2 * np][1] = r4[1];
                bq[2 * np + 1][0] = r4[2]; bq[2 * np + 1][1] = r4[3];
            }
#pragma unroll
            for (int mf = 0; mf < 2; mf++)
#pragma unroll
                for (int n = 0; n < 8; n++)
                    mma_bf16(acc[mf][n], a[mf][0], a[mf][1], a[mf][2], a[mf][3],
                             bq[n][0], bq[n][1]);
        }

        // epilogue: rs += 2^min(C2L*acc - SXL, 0)
#pragma unroll
        for (int mf = 0; mf < 2; mf++) {
#pragma unroll
            for (int n = 0; n < 8; n++) {
                float e0 = fminf(fmaf(C2L, acc[mf][n][0], -SXL), 0.f);
                float e1 = fminf(fmaf(C2L, acc[mf][n][1], -SXL), 0.f);
                float e2 = fminf(fmaf(C2L, acc[mf][n][2], -SXL), 0.f);
                float e3 = fminf(fmaf(C2L, acc[mf][n][3], -SXL), 0.f);
                rs[mf][0] += ex2f(e0) + ex2f(e1);
                rs[mf][1] += ex2f(e2) + ex2f(e3);
            }
        }
    }

    // flush: quad-reduce over tig, one atomicAdd per row
#pragma unroll
    for (int mf = 0; mf < 2; mf++) {
#pragma unroll
        for (int h = 0; h < 2; h++) {
            float v = rs[mf][h];
            v += __shfl_xor_sync(0xffffffffu, v, 1);
            v += __shfl_xor_sync(0xffffffffu, v, 2);
            if (tig == 0)
                atomicAdd(&g_Z[w * 32 + mf * 16 + h * 8 + gid], v);
        }
    }
}

// ---------------------------------------------------------------------------
// K5: out = mean_b( Dt[b] + log(Z[b]) )
// ---------------------------------------------------------------------------
__global__ void k_final(float* __restrict__ out) {
    __shared__ float sw[16];
    int tid = threadIdx.x;
    float v = g_Dt[tid] + logf(g_Z[tid]);
#pragma unroll
    for (int o = 16; o; o >>= 1) v += __shfl_xor_sync(0xffffffffu, v, o);
    if ((tid & 31) == 0) sw[tid >> 5] = v;
    __syncthreads();
    if (tid < 32) {
        float u = (tid < 16) ? sw[tid] : 0.f;
#pragma unroll
        for (int o = 8; o; o >>= 1) u += __shfl_xor_sync(0xffffffffu, u, o);
        if (tid == 0) out[0] = u / (float)BB;
    }
}

// ---------------------------------------------------------------------------
// launch
// ---------------------------------------------------------------------------
extern "C" void kernel_launch(void* const* d_in, const int* in_sizes, int n_in,
                              void* d_out, int out_size) {
    const float* X = (const float*)d_in[0];
    const int* T32 = (const int*)d_in[2];
    const float* proxies = (const float*)d_in[3];
    float* out = (float*)d_out;

    int sms = 0;
    cudaDeviceGetAttribute(&sms, cudaDevAttrMultiProcessorCount, 0);
    if (sms <= 0) sms = 148;
    cudaFuncSetAttribute(k_big, cudaFuncAttributeMaxDynamicSharedMemorySize, SMEM_BIG);
    cudaFuncSetAttribute(k_att, cudaFuncAttributeMaxDynamicSharedMemorySize, SMEM_ATT);

    k_pnorm<<<CC / 32, 256>>>(proxies);
    k_prep<<<BB, DD>>>(X, T32, proxies);
    dim3 ga(16, 16);
    k_att<<<ga, 256, SMEM_ATT>>>();
    k_xw<<<128, 256>>>();
    k_big<<<sms, 512, SMEM_BIG>>>();
    k_final<<<1, BB>>>(out);
}